// round 1
// baseline (speedup 1.0000x reference)
#include <cuda_runtime.h>

// InfoNCELoss: loss = mean_p[ logsumexp_j(dot(e_a, e_j)/T) - dot(e_a, e_t)/T ]
//              pos_sim = mean(pos pair dots), neg_sim = mean(neg pair dots)
// e = row-normalized embeddings. T = 0.07.
//
// Strategy: fixed-shift LSE (C = 1/T; self-sim term guarantees max logit ~= C),
// so the LSE GEMM needs no online max -- just exp-accumulate rows.
// All reductions are write-once (no float atomics) -> deterministic.

#define N_EMB 8192
#define D     512
#define N_POS 4096
#define N_NEG 16384

#define INV_T 14.2857142857142857f   // 1/0.07

#define N_CHUNK 16
#define COLS_PER_CHUNK (N_EMB / N_CHUNK)    // 512
#define BM 128
#define BN 64
#define BK 32
#define NT_PER_CHUNK (COLS_PER_CHUNK / BN)  // 8

// ---- device scratch (static: no allocations allowed) ----
__device__ float g_enorm[N_EMB * D];                 // 16 MB normalized embeddings
__device__ float g_posdot[N_POS];                    // dot(e_a, e_t) per pos pair
__device__ float g_negdot[N_NEG];                    // dot(e_a, e_t) per neg pair
__device__ float g_expsum_part[N_CHUNK][N_POS];      // per-column-chunk partial exp sums

static __device__ __forceinline__ float warp_sum_f(float v) {
#pragma unroll
    for (int o = 16; o; o >>= 1) v += __shfl_xor_sync(0xffffffffu, v, o);
    return v;
}
static __device__ __forceinline__ double warp_sum_d(double v) {
#pragma unroll
    for (int o = 16; o; o >>= 1) v += __shfl_xor_sync(0xffffffffu, v, o);
    return v;
}

// ---------------------------------------------------------------------------
// 1) Row-normalize embeddings: one block per row, 128 threads (4 floats each).
// ---------------------------------------------------------------------------
__global__ void normalize_kernel(const float* __restrict__ emb) {
    const int row = blockIdx.x;
    const int t = threadIdx.x;  // 0..127
    float4 a = reinterpret_cast<const float4*>(emb + (size_t)row * D)[t];
    float ss = a.x * a.x + a.y * a.y + a.z * a.z + a.w * a.w;
    ss = warp_sum_f(ss);
    __shared__ float ws[4];
    if ((t & 31) == 0) ws[t >> 5] = ss;
    __syncthreads();
    float tot = ws[0] + ws[1] + ws[2] + ws[3];
    float inv = 1.0f / fmaxf(sqrtf(tot), 1e-8f);
    float4 o4 = make_float4(a.x * inv, a.y * inv, a.z * inv, a.w * inv);
    reinterpret_cast<float4*>(g_enorm + (size_t)row * D)[t] = o4;
}

// ---------------------------------------------------------------------------
// 2) Pair dots: one warp per pair. First 4096 warps = pos, next 16384 = neg.
// ---------------------------------------------------------------------------
__global__ void pairs_kernel(const int* __restrict__ pa, const int* __restrict__ pt,
                             const int* __restrict__ na, const int* __restrict__ nt) {
    const int w = (blockIdx.x * blockDim.x + threadIdx.x) >> 5;
    const int lane = threadIdx.x & 31;
    int ai, ti;
    bool is_pos;
    if (w < N_POS) {
        ai = pa[w]; ti = pt[w]; is_pos = true;
    } else {
        int q = w - N_POS;
        if (q >= N_NEG) return;
        ai = na[q]; ti = nt[q]; is_pos = false;
    }
    const float4* va = reinterpret_cast<const float4*>(g_enorm + (size_t)ai * D);
    const float4* vb = reinterpret_cast<const float4*>(g_enorm + (size_t)ti * D);
    float s = 0.f;
#pragma unroll
    for (int i = 0; i < 4; i++) {
        float4 x = va[lane + 32 * i];
        float4 y = vb[lane + 32 * i];
        s += x.x * y.x + x.y * y.y + x.z * y.z + x.w * y.w;
    }
    s = warp_sum_f(s);
    if (lane == 0) {
        if (is_pos) g_posdot[w] = s;
        else        g_negdot[w - N_POS] = s;
    }
}

// ---------------------------------------------------------------------------
// 3) LSE GEMM: C[p, j] = dot(e[pa[p]], e[j]); accumulate exp(C*INV_T - INV_T)
//    per row. Grid: (N_POS/BM) x N_CHUNK. Each block: BM rows x 512 cols.
//    Tiling: BM=128, BN=64, BK=32; 256 threads, 8x4 register tile each.
// ---------------------------------------------------------------------------
__global__ __launch_bounds__(256) void lse_gemm_kernel(const int* __restrict__ pa) {
    __shared__ float As[BK][BM + 4];   // [k][m]
    __shared__ float Bs[BK][BN + 4];   // [k][n]
    __shared__ int arow[BM];

    const int tid = threadIdx.x;
    const int tx = tid & 15;           // 0..15 -> 4 cols each
    const int ty = tid >> 4;           // 0..15 -> 8 rows each
    const int p0 = blockIdx.x * BM;
    const int j0 = blockIdx.y * COLS_PER_CHUNK;

    if (tid < BM) arow[tid] = pa[p0 + tid];
    __syncthreads();

    // A-tile load map: 1024 float4 per tile -> 4 per thread.
    const float* aptr[4];
    int afr[4], afk[4];
#pragma unroll
    for (int i = 0; i < 4; i++) {
        int f = tid + 256 * i;
        afr[i] = f >> 3;           // row within tile 0..127
        afk[i] = (f & 7) * 4;      // k offset within tile 0..28
        aptr[i] = g_enorm + (size_t)arow[afr[i]] * D + afk[i];
    }
    // B-tile load map: 512 float4 per tile -> 2 per thread.
    int bfr[2], bfk[2];
#pragma unroll
    for (int i = 0; i < 2; i++) {
        int f = tid + 256 * i;
        bfr[i] = f >> 3;           // col within tile 0..63
        bfk[i] = (f & 7) * 4;
    }

    float rsum[8];
#pragma unroll
    for (int i = 0; i < 8; i++) rsum[i] = 0.f;

    for (int ntile = 0; ntile < NT_PER_CHUNK; ntile++) {
        const int jb = j0 + ntile * BN;
        float acc[8][4];
#pragma unroll
        for (int i = 0; i < 8; i++)
#pragma unroll
            for (int j = 0; j < 4; j++) acc[i][j] = 0.f;

        float4 aReg[4], bReg[2];
#pragma unroll
        for (int i = 0; i < 4; i++) aReg[i] = *reinterpret_cast<const float4*>(aptr[i]);
#pragma unroll
        for (int i = 0; i < 2; i++)
            bReg[i] = *reinterpret_cast<const float4*>(
                g_enorm + (size_t)(jb + bfr[i]) * D + bfk[i]);

        for (int kt = 0; kt < D / BK; kt++) {
            // regs -> smem (transposed to [k][m]/[k][n])
#pragma unroll
            for (int i = 0; i < 4; i++) {
                As[afk[i] + 0][afr[i]] = aReg[i].x;
                As[afk[i] + 1][afr[i]] = aReg[i].y;
                As[afk[i] + 2][afr[i]] = aReg[i].z;
                As[afk[i] + 3][afr[i]] = aReg[i].w;
            }
#pragma unroll
            for (int i = 0; i < 2; i++) {
                Bs[bfk[i] + 0][bfr[i]] = bReg[i].x;
                Bs[bfk[i] + 1][bfr[i]] = bReg[i].y;
                Bs[bfk[i] + 2][bfr[i]] = bReg[i].z;
                Bs[bfk[i] + 3][bfr[i]] = bReg[i].w;
            }
            __syncthreads();

            // prefetch next k-tile while computing this one
            if (kt + 1 < D / BK) {
                const int ko = (kt + 1) * BK;
#pragma unroll
                for (int i = 0; i < 4; i++)
                    aReg[i] = *reinterpret_cast<const float4*>(aptr[i] + ko);
#pragma unroll
                for (int i = 0; i < 2; i++)
                    bReg[i] = *reinterpret_cast<const float4*>(
                        g_enorm + (size_t)(jb + bfr[i]) * D + ko + bfk[i]);
            }

#pragma unroll
            for (int k = 0; k < BK; k++) {
                float4 a0 = *reinterpret_cast<const float4*>(&As[k][ty * 8]);
                float4 a1 = *reinterpret_cast<const float4*>(&As[k][ty * 8 + 4]);
                float4 b  = *reinterpret_cast<const float4*>(&Bs[k][tx * 4]);
                float av[8] = {a0.x, a0.y, a0.z, a0.w, a1.x, a1.y, a1.z, a1.w};
                float bv[4] = {b.x, b.y, b.z, b.w};
#pragma unroll
                for (int ii = 0; ii < 8; ii++)
#pragma unroll
                    for (int jj = 0; jj < 4; jj++)
                        acc[ii][jj] = fmaf(av[ii], bv[jj], acc[ii][jj]);
            }
            __syncthreads();
        }

        // epilogue: exp(logit - C), C = INV_T  =>  (acc - 1) * INV_T
#pragma unroll
        for (int i = 0; i < 8; i++)
#pragma unroll
            for (int j = 0; j < 4; j++)
                rsum[i] += __expf(fmaf(acc[i][j], INV_T, -INV_T));
    }

    // deterministic per-row reduction across the 16 tx lanes (reuse As smem)
    __syncthreads();
    float* red = &As[0][0];   // 128*16 = 2048 floats < 32*132
#pragma unroll
    for (int i = 0; i < 8; i++) red[(ty * 8 + i) * 16 + tx] = rsum[i];
    __syncthreads();
    if (tid < BM) {
        float s = 0.f;
#pragma unroll
        for (int c = 0; c < 16; c++) s += red[tid * 16 + c];
        g_expsum_part[blockIdx.y][p0 + tid] = s;
    }
}

// ---------------------------------------------------------------------------
// 4) Finalize: loss = mean(C + log(expsum) - posdot*C'), pos/neg sims = means.
// ---------------------------------------------------------------------------
__global__ void finalize_kernel(float* __restrict__ out, int out_size) {
    const int tid = threadIdx.x;
    double s_loss = 0.0, s_pos = 0.0, s_neg = 0.0;

    for (int p = tid; p < N_POS; p += 256) {
        float es = 0.f;
#pragma unroll
        for (int c = 0; c < N_CHUNK; c++) es += g_expsum_part[c][p];
        float pd = g_posdot[p];
        s_loss += (double)logf(es) - (double)pd * (1.0 / 0.07);
        s_pos  += (double)pd;
    }
    for (int q = tid; q < N_NEG; q += 256) s_neg += (double)g_negdot[q];

    s_loss = warp_sum_d(s_loss);
    s_pos  = warp_sum_d(s_pos);
    s_neg  = warp_sum_d(s_neg);

    __shared__ double sh[3][8];
    const int lane = tid & 31, w = tid >> 5;
    if (lane == 0) { sh[0][w] = s_loss; sh[1][w] = s_pos; sh[2][w] = s_neg; }
    __syncthreads();
    if (tid == 0) {
        double L = 0, P = 0, Ng = 0;
#pragma unroll
        for (int i = 0; i < 8; i++) { L += sh[0][i]; P += sh[1][i]; Ng += sh[2][i]; }
        out[0] = (float)(L / N_POS + 1.0 / 0.07);   // + fixed shift C
        out[1] = (float)(P / N_POS);
        out[2] = (float)(Ng / N_NEG);
    }
    for (int i = 3 + tid; i < out_size; i += 256) out[i] = 0.f;
}

// ---------------------------------------------------------------------------
extern "C" void kernel_launch(void* const* d_in, const int* in_sizes, int n_in,
                              void* d_out, int out_size) {
    const float* emb = (const float*)d_in[0];
    const int* pa = (const int*)d_in[1];
    const int* pt = (const int*)d_in[2];
    const int* na = (const int*)d_in[3];
    const int* nt = (const int*)d_in[4];
    float* out = (float*)d_out;
    (void)in_sizes; (void)n_in;

    normalize_kernel<<<N_EMB, 128>>>(emb);

    // (4096 + 16384) pairs, 1 warp each, 8 warps/block -> 2560 blocks
    pairs_kernel<<<(N_POS + N_NEG) / 8, 256>>>(pa, pt, na, nt);

    dim3 grid(N_POS / BM, N_CHUNK);
    lse_gemm_kernel<<<grid, 256>>>(pa);

    finalize_kernel<<<1, 256>>>(out, out_size);
}

// round 5
// speedup vs baseline: 5.4946x; 5.4946x over previous
#include <cuda_runtime.h>
#include <cuda_bf16.h>
#include <mma.h>
#include <cstdint>

using namespace nvcuda;

// InfoNCELoss via WMMA bf16 tensor cores (intrinsics only — no inline asm in
// the hot path; tcgen05 unavailable: harness targets sm_100, not sm_100a).
//
// loss = mean_p[ LSE_j(dot(e_a,e_j)/T) - dot(e_a,e_t)/T ],  e row-normalized.
// Fixed-shift LSE: C = 1/T (self-sim logit == C exactly), so
//   LSE = C + log(sum_j exp(logit_j - C)).  Exact identity, no online max.
// GEMM inputs bf16 (products exact, fp32 accum); pos_sim/neg_sim/pos_logit on
// an exact fp32 pair-dot path. All reductions write-once -> deterministic.

#define N_EMB 8192
#define D     512
#define N_POS 4096
#define N_NEG 16384
#define INV_T   14.2857142857142857f
#define INV_T_D 14.285714285714285714

// ---- GEMM tiling ----
#define BM 128
#define BN 128
#define BK 32
#define NKT (D / BK)            // 16 k-stages
#define NMT (N_POS / BM)        // 32
#define NNT (N_EMB / BN)        // 64
#define ASTR 40                 // padded smem row stride in bf16 (80 B)

// ---- device scratch ----
__device__ float          g_enorm[N_EMB * D];
__device__ __nv_bfloat16  g_ebf[N_EMB * D];
__device__ float          g_posdot[N_POS];
__device__ float          g_negdot[N_NEG];
__device__ float          g_part[NNT][N_POS];
__device__ double         g_red[48][3];

static __device__ __forceinline__ float warp_sum_f(float v) {
#pragma unroll
    for (int o = 16; o; o >>= 1) v += __shfl_xor_sync(0xffffffffu, v, o);
    return v;
}
static __device__ __forceinline__ double warp_sum_d(double v) {
#pragma unroll
    for (int o = 16; o; o >>= 1) v += __shfl_xor_sync(0xffffffffu, v, o);
    return v;
}

// ---------------------------------------------------------------------------
// 1) Normalize rows; emit fp32 (exact pair dots) and bf16 (MMA).
// ---------------------------------------------------------------------------
__global__ void normalize_kernel(const float* __restrict__ emb) {
    const int row = blockIdx.x;
    const int t = threadIdx.x;  // 0..127
    float4 a = reinterpret_cast<const float4*>(emb + (size_t)row * D)[t];
    float ss = a.x * a.x + a.y * a.y + a.z * a.z + a.w * a.w;
    ss = warp_sum_f(ss);
    __shared__ float ws[4];
    if ((t & 31) == 0) ws[t >> 5] = ss;
    __syncthreads();
    float inv = 1.0f / fmaxf(sqrtf(ws[0] + ws[1] + ws[2] + ws[3]), 1e-8f);
    float4 o4 = make_float4(a.x * inv, a.y * inv, a.z * inv, a.w * inv);
    reinterpret_cast<float4*>(g_enorm + (size_t)row * D)[t] = o4;
    __nv_bfloat162 b0 = __floats2bfloat162_rn(o4.x, o4.y);
    __nv_bfloat162 b1 = __floats2bfloat162_rn(o4.z, o4.w);
    uint2 pk = make_uint2(*(uint32_t*)&b0, *(uint32_t*)&b1);
    reinterpret_cast<uint2*>(g_ebf + (size_t)row * D)[t] = pk;
}

// ---------------------------------------------------------------------------
// 2) Pair dots in fp32 (precision-critical). One warp per pair.
// ---------------------------------------------------------------------------
__global__ void pairs_kernel(const int* __restrict__ pa, const int* __restrict__ pt,
                             const int* __restrict__ na, const int* __restrict__ nt) {
    const int w = (blockIdx.x * blockDim.x + threadIdx.x) >> 5;
    const int lane = threadIdx.x & 31;
    int ai, ti;
    bool is_pos;
    if (w < N_POS) { ai = pa[w]; ti = pt[w]; is_pos = true; }
    else {
        int q = w - N_POS;
        if (q >= N_NEG) return;
        ai = na[q]; ti = nt[q]; is_pos = false;
    }
    const float4* va = reinterpret_cast<const float4*>(g_enorm + (size_t)ai * D);
    const float4* vb = reinterpret_cast<const float4*>(g_enorm + (size_t)ti * D);
    float s = 0.f;
#pragma unroll
    for (int i = 0; i < 4; i++) {
        float4 x = va[lane + 32 * i];
        float4 y = vb[lane + 32 * i];
        s += x.x * y.x + x.y * y.y + x.z * y.z + x.w * y.w;
    }
    s = warp_sum_f(s);
    if (lane == 0) {
        if (is_pos) g_posdot[w] = s;
        else        g_negdot[w - N_POS] = s;
    }
}

// ---------------------------------------------------------------------------
// 3) LSE GEMM via WMMA bf16. Block 128x128, K in 16 stages of 32, register
//    double-buffered loads (Round-1-proven pattern). 8 warps = 4(m) x 2(n),
//    warp tile 32x64 = 2x4 wmma 16x16x16 fragments.
//    Epilogue: store_matrix_sync -> per-warp scratch -> exp + row sums.
// ---------------------------------------------------------------------------
__global__ __launch_bounds__(256) void lse_gemm_wmma(const int* __restrict__ pa) {
    __shared__ __align__(16) __nv_bfloat16 smA[2][BM][ASTR];   // 20480 B
    __shared__ __align__(16) __nv_bfloat16 smB[2][BN][ASTR];   // 20480 B
    __shared__ int arow[BM];
    __shared__ float red[BM][2];

    const int tid = threadIdx.x;
    const int wid = tid >> 5;
    const int lane = tid & 31;
    const int p0 = blockIdx.x * BM;
    const int j0 = blockIdx.y * BN;
    const int warp_m = wid & 3;       // rows warp_m*32 .. +32
    const int warp_n = wid >> 2;      // cols warp_n*64 .. +64

    if (tid < BM) arow[tid] = pa[p0 + tid];
    __syncthreads();

    // ---- load maps: per stage A/B are 512 16B-chunks each -> 2+2 per thread.
    // chunk f: row = f>>2 (0..127), kchunk = f&3 (8 bf16 each).
    const __nv_bfloat16* asrc[2];
    const __nv_bfloat16* bsrc[2];
    int ar[2], akc[2];
#pragma unroll
    for (int i = 0; i < 2; i++) {
        int f = tid + 256 * i;
        ar[i] = f >> 2; akc[i] = (f & 3) * 8;
        asrc[i] = g_ebf + (size_t)arow[ar[i]] * D + akc[i];
        bsrc[i] = g_ebf + (size_t)(j0 + ar[i]) * D + akc[i];
    }

    wmma::fragment<wmma::accumulator, 16, 16, 16, float> acc[2][4];
#pragma unroll
    for (int mt = 0; mt < 2; mt++)
#pragma unroll
        for (int nt = 0; nt < 4; nt++) wmma::fill_fragment(acc[mt][nt], 0.0f);

    // prologue: stage 0 into registers
    uint4 avr[2], bvr[2];
#pragma unroll
    for (int i = 0; i < 2; i++) {
        avr[i] = *reinterpret_cast<const uint4*>(asrc[i]);
        bvr[i] = *reinterpret_cast<const uint4*>(bsrc[i]);
    }

    for (int kt = 0; kt < NKT; kt++) {
        const int buf = kt & 1;
        // regs -> smem
#pragma unroll
        for (int i = 0; i < 2; i++) {
            *reinterpret_cast<uint4*>(&smA[buf][ar[i]][akc[i]]) = avr[i];
            *reinterpret_cast<uint4*>(&smB[buf][ar[i]][akc[i]]) = bvr[i];
        }
        __syncthreads();

        // prefetch next stage into registers (overlaps with compute below)
        if (kt + 1 < NKT) {
            const int ko = (kt + 1) * BK;
#pragma unroll
            for (int i = 0; i < 2; i++) {
                avr[i] = *reinterpret_cast<const uint4*>(asrc[i] + ko);
                bvr[i] = *reinterpret_cast<const uint4*>(bsrc[i] + ko);
            }
        }

        // compute this stage: 2 k-steps of 16
#pragma unroll
        for (int ks = 0; ks < BK; ks += 16) {
            wmma::fragment<wmma::matrix_b, 16, 16, 16, __nv_bfloat16, wmma::col_major> bf[4];
#pragma unroll
            for (int nt = 0; nt < 4; nt++)
                wmma::load_matrix_sync(bf[nt], &smB[buf][warp_n * 64 + nt * 16][ks], ASTR);
#pragma unroll
            for (int mt = 0; mt < 2; mt++) {
                wmma::fragment<wmma::matrix_a, 16, 16, 16, __nv_bfloat16, wmma::row_major> af;
                wmma::load_matrix_sync(af, &smA[buf][warp_m * 32 + mt * 16][ks], ASTR);
#pragma unroll
                for (int nt = 0; nt < 4; nt++)
                    wmma::mma_sync(acc[mt][nt], af, bf[nt], acc[mt][nt]);
            }
        }
        __syncthreads();
    }

    // ---- epilogue: exp((logit-1)*INV_T), per-row sums -> write-once partials.
    // Scratch aliases smA (dead after the loop + syncthreads above).
    float* scr = reinterpret_cast<float*>(&smA[0][0][0]) + wid * (16 * 20);
#pragma unroll
    for (int mt = 0; mt < 2; mt++) {
        float rs = 0.f;
        const int row = lane >> 1, half = lane & 1;
#pragma unroll
        for (int nt = 0; nt < 4; nt++) {
            __syncwarp();
            wmma::store_matrix_sync(scr, acc[mt][nt], 20, wmma::mem_row_major);
            __syncwarp();
            const float* rp = scr + row * 20 + half * 8;
#pragma unroll
            for (int i = 0; i < 8; i++)
                rs += __expf(fmaf(rp[i], INV_T, -INV_T));
        }
        rs += __shfl_xor_sync(0xffffffffu, rs, 1);   // combine col halves
        if (half == 0)
            red[warp_m * 32 + mt * 16 + row][warp_n] = rs;
    }
    __syncthreads();
    if (tid < BM)
        g_part[blockIdx.y][p0 + tid] = red[tid][0] + red[tid][1];
}

// ---------------------------------------------------------------------------
// 4) Parallel reduce: blocks 0..15 pos rows (loss, pos_sim), 16..47 neg.
// ---------------------------------------------------------------------------
__global__ void reduce_kernel() {
    const int b = blockIdx.x, t = threadIdx.x;
    double v0 = 0.0, v1 = 0.0, v2 = 0.0;
    if (b < 16) {
        const int p = b * 256 + t;
        float es = 0.f;
#pragma unroll
        for (int c = 0; c < NNT; c++) es += g_part[c][p];
        const float pd = g_posdot[p];
        v0 = (double)logf(es) - (double)pd * INV_T_D;
        v1 = (double)pd;
    } else {
        const int q = (b - 16) * 512 + t;
        v2 = (double)g_negdot[q] + (double)g_negdot[q + 256];
    }
    v0 = warp_sum_d(v0); v1 = warp_sum_d(v1); v2 = warp_sum_d(v2);
    __shared__ double sh[3][8];
    if ((t & 31) == 0) { sh[0][t >> 5] = v0; sh[1][t >> 5] = v1; sh[2][t >> 5] = v2; }
    __syncthreads();
    if (t == 0) {
        double a = 0, bb = 0, c = 0;
#pragma unroll
        for (int i = 0; i < 8; i++) { a += sh[0][i]; bb += sh[1][i]; c += sh[2][i]; }
        g_red[b][0] = a; g_red[b][1] = bb; g_red[b][2] = c;
    }
}

__global__ void final_kernel(float* __restrict__ out, int out_size) {
    if (threadIdx.x == 0) {
        double L = 0, P = 0, Ng = 0;
        for (int i = 0; i < 48; i++) { L += g_red[i][0]; P += g_red[i][1]; Ng += g_red[i][2]; }
        out[0] = (float)(L / N_POS + INV_T_D);
        out[1] = (float)(P / N_POS);
        out[2] = (float)(Ng / N_NEG);
    }
    for (int i = 3 + threadIdx.x; i < out_size; i += blockDim.x) out[i] = 0.f;
}

// ---------------------------------------------------------------------------
extern "C" void kernel_launch(void* const* d_in, const int* in_sizes, int n_in,
                              void* d_out, int out_size) {
    const float* emb = (const float*)d_in[0];
    const int* pa = (const int*)d_in[1];
    const int* pt = (const int*)d_in[2];
    const int* na = (const int*)d_in[3];
    const int* nt = (const int*)d_in[4];
    float* out = (float*)d_out;
    (void)in_sizes; (void)n_in;

    normalize_kernel<<<N_EMB, 128>>>(emb);
    pairs_kernel<<<(N_POS + N_NEG) / 8, 256>>>(pa, pt, na, nt);

    dim3 grid(NMT, NNT);
    lse_gemm_wmma<<<grid, 256>>>(pa);

    reduce_kernel<<<48, 256>>>();
    final_kernel<<<1, 64>>>(out, out_size);
}

// round 6
// speedup vs baseline: 5.8184x; 1.0589x over previous
#include <cuda_runtime.h>
#include <cuda_bf16.h>
#include <cuda_pipeline.h>
#include <mma.h>
#include <cstdint>

using namespace nvcuda;

// InfoNCELoss via WMMA bf16 tensor cores + cp.async intrinsic pipeline.
// (No inline asm anywhere: tcgen05 unavailable — harness targets sm_100 — and
//  the intrinsic-only kernels are the ones that run in this harness.)
//
// loss = mean_p[ LSE_j(dot(e_a,e_j)/T) - dot(e_a,e_t)/T ],  e row-normalized.
// Fixed-shift LSE: C = 1/T (self-sim logit == C exactly), so
//   LSE = C + log(sum_j exp(logit_j - C)).  Exact identity, no online max.
// GEMM inputs bf16 (products exact, fp32 accum); pos_sim/neg_sim/pos_logit on
// an exact fp32 pair-dot path. All reductions write-once -> deterministic.

#define N_EMB 8192
#define D     512
#define N_POS 4096
#define N_NEG 16384
#define INV_T   14.2857142857142857f
#define INV_T_D 14.285714285714285714

// ---- GEMM tiling ----
#define BM 128
#define BN 128
#define BK 32
#define NKT (D / BK)            // 16 k-stages
#define NMT (N_POS / BM)        // 32
#define NNT (N_EMB / BN)        // 64
#define ASTR 40                 // padded smem row stride in bf16 (80 B)
#define STAGES 4
#define STAGE_BYTES (BM * ASTR * 2)             // 10240 B per operand stage
#define SM_A_OFF 0
#define SM_B_OFF (STAGES * STAGE_BYTES)         // 40960
#define SM_AROW_OFF (2 * STAGES * STAGE_BYTES)  // 81920
#define SM_RED_OFF (SM_AROW_OFF + BM * 4)       // 82432
#define SMEM_TOTAL (SM_RED_OFF + BM * 2 * 4)    // 83456 B

// ---- device scratch ----
__device__ float          g_enorm[N_EMB * D];
__device__ __nv_bfloat16  g_ebf[N_EMB * D];
__device__ float          g_posdot[N_POS];
__device__ float          g_negdot[N_NEG];
__device__ float          g_part[NNT][N_POS];
__device__ double         g_red[48][3];

static __device__ __forceinline__ float warp_sum_f(float v) {
#pragma unroll
    for (int o = 16; o; o >>= 1) v += __shfl_xor_sync(0xffffffffu, v, o);
    return v;
}
static __device__ __forceinline__ double warp_sum_d(double v) {
#pragma unroll
    for (int o = 16; o; o >>= 1) v += __shfl_xor_sync(0xffffffffu, v, o);
    return v;
}

// ---------------------------------------------------------------------------
// 1) Normalize rows; emit fp32 (exact pair dots) and bf16 (MMA).
// ---------------------------------------------------------------------------
__global__ void normalize_kernel(const float* __restrict__ emb) {
    const int row = blockIdx.x;
    const int t = threadIdx.x;  // 0..127
    float4 a = reinterpret_cast<const float4*>(emb + (size_t)row * D)[t];
    float ss = a.x * a.x + a.y * a.y + a.z * a.z + a.w * a.w;
    ss = warp_sum_f(ss);
    __shared__ float ws[4];
    if ((t & 31) == 0) ws[t >> 5] = ss;
    __syncthreads();
    float inv = 1.0f / fmaxf(sqrtf(ws[0] + ws[1] + ws[2] + ws[3]), 1e-8f);
    float4 o4 = make_float4(a.x * inv, a.y * inv, a.z * inv, a.w * inv);
    reinterpret_cast<float4*>(g_enorm + (size_t)row * D)[t] = o4;
    __nv_bfloat162 b0 = __floats2bfloat162_rn(o4.x, o4.y);
    __nv_bfloat162 b1 = __floats2bfloat162_rn(o4.z, o4.w);
    uint2 pk = make_uint2(*(uint32_t*)&b0, *(uint32_t*)&b1);
    reinterpret_cast<uint2*>(g_ebf + (size_t)row * D)[t] = pk;
}

// ---------------------------------------------------------------------------
// 2) Pair dots in fp32 (precision-critical). One warp per pair.
// ---------------------------------------------------------------------------
__global__ void pairs_kernel(const int* __restrict__ pa, const int* __restrict__ pt,
                             const int* __restrict__ na, const int* __restrict__ nt) {
    const int w = (blockIdx.x * blockDim.x + threadIdx.x) >> 5;
    const int lane = threadIdx.x & 31;
    int ai, ti;
    bool is_pos;
    if (w < N_POS) { ai = pa[w]; ti = pt[w]; is_pos = true; }
    else {
        int q = w - N_POS;
        if (q >= N_NEG) return;
        ai = na[q]; ti = nt[q]; is_pos = false;
    }
    const float4* va = reinterpret_cast<const float4*>(g_enorm + (size_t)ai * D);
    const float4* vb = reinterpret_cast<const float4*>(g_enorm + (size_t)ti * D);
    float s = 0.f;
#pragma unroll
    for (int i = 0; i < 4; i++) {
        float4 x = va[lane + 32 * i];
        float4 y = vb[lane + 32 * i];
        s += x.x * y.x + x.y * y.y + x.z * y.z + x.w * y.w;
    }
    s = warp_sum_f(s);
    if (lane == 0) {
        if (is_pos) g_posdot[w] = s;
        else        g_negdot[w - N_POS] = s;
    }
}

// ---------------------------------------------------------------------------
// 3) LSE GEMM via WMMA bf16 + 4-stage cp.async pipeline (intrinsics).
//    Block 128x128, BK=32. 8 warps = 4(m) x 2(n), warp tile 32x64.
// ---------------------------------------------------------------------------
__global__ __launch_bounds__(256) void lse_gemm_wmma(const int* __restrict__ pa) {
    extern __shared__ __align__(16) char sm[];
    __nv_bfloat16* smA = reinterpret_cast<__nv_bfloat16*>(sm + SM_A_OFF);
    __nv_bfloat16* smB = reinterpret_cast<__nv_bfloat16*>(sm + SM_B_OFF);
    int*   arow = reinterpret_cast<int*>(sm + SM_AROW_OFF);
    float* red  = reinterpret_cast<float*>(sm + SM_RED_OFF);   // [BM][2]

    const int tid = threadIdx.x;
    const int wid = tid >> 5;
    const int lane = tid & 31;
    const int p0 = blockIdx.x * BM;
    const int j0 = blockIdx.y * BN;
    const int warp_m = wid & 3;       // rows warp_m*32 .. +32
    const int warp_n = wid >> 2;      // cols warp_n*64 .. +64

    if (tid < BM) arow[tid] = pa[p0 + tid];
    __syncthreads();

    // ---- copy maps: per stage A/B are 512 16B-chunks each -> 2+2 per thread.
    const __nv_bfloat16* asrc[2];
    const __nv_bfloat16* bsrc[2];
    int soff[2];   // byte offset within a stage buffer
#pragma unroll
    for (int i = 0; i < 2; i++) {
        int f = tid + 256 * i;
        int r = f >> 2, kc = (f & 3) * 8;
        asrc[i] = g_ebf + (size_t)arow[r] * D + kc;
        bsrc[i] = g_ebf + (size_t)(j0 + r) * D + kc;
        soff[i] = r * (ASTR * 2) + kc * 2;
    }

    // issue one stage's copies as one commit group
    auto issue = [&](int kt) {
        const int buf = kt & (STAGES - 1);
        const int ko = kt * BK;
        char* da = (char*)smA + buf * STAGE_BYTES;
        char* db = (char*)smB + buf * STAGE_BYTES;
#pragma unroll
        for (int i = 0; i < 2; i++) {
            __pipeline_memcpy_async(da + soff[i], asrc[i] + ko, 16);
            __pipeline_memcpy_async(db + soff[i], bsrc[i] + ko, 16);
        }
        __pipeline_commit();
    };

    wmma::fragment<wmma::accumulator, 16, 16, 16, float> acc[2][4];
#pragma unroll
    for (int mt = 0; mt < 2; mt++)
#pragma unroll
        for (int nt = 0; nt < 4; nt++) wmma::fill_fragment(acc[mt][nt], 0.0f);

    // prologue: stages 0..STAGES-2 in flight
#pragma unroll
    for (int s = 0; s < STAGES - 1; s++) issue(s);

    for (int kt = 0; kt < NKT; kt++) {
        const int buf = kt & (STAGES - 1);
        __pipeline_wait_prior(STAGES - 2);   // stage kt complete
        __syncthreads();                     // visible to all; prev compute done

        // keep group count uniform: empty commit in the tail
        if (kt + STAGES - 1 < NKT) issue(kt + STAGES - 1);
        else __pipeline_commit();

        const __nv_bfloat16* A = smA + buf * (BM * ASTR);
        const __nv_bfloat16* B = smB + buf * (BN * ASTR);
#pragma unroll
        for (int ks = 0; ks < BK; ks += 16) {
            wmma::fragment<wmma::matrix_b, 16, 16, 16, __nv_bfloat16, wmma::col_major> bf[4];
#pragma unroll
            for (int nt = 0; nt < 4; nt++)
                wmma::load_matrix_sync(bf[nt], B + (warp_n * 64 + nt * 16) * ASTR + ks, ASTR);
#pragma unroll
            for (int mt = 0; mt < 2; mt++) {
                wmma::fragment<wmma::matrix_a, 16, 16, 16, __nv_bfloat16, wmma::row_major> af;
                wmma::load_matrix_sync(af, A + (warp_m * 32 + mt * 16) * ASTR + ks, ASTR);
#pragma unroll
                for (int nt = 0; nt < 4; nt++)
                    wmma::mma_sync(acc[mt][nt], af, bf[nt], acc[mt][nt]);
            }
        }
    }
    __syncthreads();   // all compute done before scratch aliasing

    // ---- epilogue: exp((logit-1)*INV_T), per-row sums -> write-once partials.
    // Scratch aliases stage buffers (dead now).
    float* scr = reinterpret_cast<float*>(sm) + wid * (16 * 20);
#pragma unroll
    for (int mt = 0; mt < 2; mt++) {
        float rs = 0.f;
        const int row = lane >> 1, half = lane & 1;
#pragma unroll
        for (int nt = 0; nt < 4; nt++) {
            __syncwarp();
            wmma::store_matrix_sync(scr, acc[mt][nt], 20, wmma::mem_row_major);
            __syncwarp();
            const float* rp = scr + row * 20 + half * 8;
#pragma unroll
            for (int i = 0; i < 8; i++)
                rs += __expf(fmaf(rp[i], INV_T, -INV_T));
        }
        rs += __shfl_xor_sync(0xffffffffu, rs, 1);   // combine col halves
        if (half == 0)
            red[(warp_m * 32 + mt * 16 + row) * 2 + warp_n] = rs;
    }
    __syncthreads();
    if (tid < BM)
        g_part[blockIdx.y][p0 + tid] = red[tid * 2 + 0] + red[tid * 2 + 1];
}

// ---------------------------------------------------------------------------
// 4) Parallel reduce: blocks 0..15 pos rows (loss, pos_sim), 16..47 neg.
// ---------------------------------------------------------------------------
__global__ void reduce_kernel() {
    const int b = blockIdx.x, t = threadIdx.x;
    double v0 = 0.0, v1 = 0.0, v2 = 0.0;
    if (b < 16) {
        const int p = b * 256 + t;
        float es = 0.f;
#pragma unroll
        for (int c = 0; c < NNT; c++) es += g_part[c][p];
        const float pd = g_posdot[p];
        v0 = (double)logf(es) - (double)pd * INV_T_D;
        v1 = (double)pd;
    } else {
        const int q = (b - 16) * 512 + t;
        v2 = (double)g_negdot[q] + (double)g_negdot[q + 256];
    }
    v0 = warp_sum_d(v0); v1 = warp_sum_d(v1); v2 = warp_sum_d(v2);
    __shared__ double sh[3][8];
    if ((t & 31) == 0) { sh[0][t >> 5] = v0; sh[1][t >> 5] = v1; sh[2][t >> 5] = v2; }
    __syncthreads();
    if (t == 0) {
        double a = 0, bb = 0, c = 0;
#pragma unroll
        for (int i = 0; i < 8; i++) { a += sh[0][i]; bb += sh[1][i]; c += sh[2][i]; }
        g_red[b][0] = a; g_red[b][1] = bb; g_red[b][2] = c;
    }
}

__global__ void final_kernel(float* __restrict__ out, int out_size) {
    if (threadIdx.x == 0) {
        double L = 0, P = 0, Ng = 0;
        for (int i = 0; i < 48; i++) { L += g_red[i][0]; P += g_red[i][1]; Ng += g_red[i][2]; }
        out[0] = (float)(L / N_POS + INV_T_D);
        out[1] = (float)(P / N_POS);
        out[2] = (float)(Ng / N_NEG);
    }
    for (int i = 3 + threadIdx.x; i < out_size; i += blockDim.x) out[i] = 0.f;
}

// ---------------------------------------------------------------------------
extern "C" void kernel_launch(void* const* d_in, const int* in_sizes, int n_in,
                              void* d_out, int out_size) {
    const float* emb = (const float*)d_in[0];
    const int* pa = (const int*)d_in[1];
    const int* pt = (const int*)d_in[2];
    const int* na = (const int*)d_in[3];
    const int* nt = (const int*)d_in[4];
    float* out = (float*)d_out;
    (void)in_sizes; (void)n_in;

    // host-side attribute set: immediate, deterministic, not stream-ordered
    cudaFuncSetAttribute(lse_gemm_wmma,
                         cudaFuncAttributeMaxDynamicSharedMemorySize, SMEM_TOTAL);

    normalize_kernel<<<N_EMB, 128>>>(emb);
    pairs_kernel<<<(N_POS + N_NEG) / 8, 256>>>(pa, pt, na, nt);

    dim3 grid(NMT, NNT);
    lse_gemm_wmma<<<grid, 256, SMEM_TOTAL>>>(pa);

    reduce_kernel<<<48, 256>>>();
    final_kernel<<<1, 64>>>(out, out_size);
}